// round 7
// baseline (speedup 1.0000x reference)
#include <cuda_runtime.h>

// Fixed shapes: B=2, H=8, S=256, d=64
#define NB 2
#define NH 8
#define NS 256
#define ND 64
#define PER_B (NH*NS*ND)      // 131072 floats per batch in Q/V
#define OUT_HALF (NB*PER_B)   // 262144 floats: attn offset (context first, attn second)

// Single-pass kernel: 128 blocks = (b, h, s7). Each block is self-sufficient:
//   base_row(s_hi) = base0 + s_hi,  base0 = (32*(2*s7+h) + 256) & 511
// All 32 rows' score windows lie in one contiguous u-range of <= 95 values,
// so the block computes W[u][e] = sum_r Q*V for just that range (all 64 e),
// prefix-sums it in smem, and finishes softmax + outputs with no cross-block
// communication whatsoever.
__global__ void __launch_bounds__(256) k_onepass(const float* __restrict__ Q,
                                                 const float* __restrict__ V,
                                                 float* __restrict__ out) {
    __shared__ float Wsm[96][64];   // [u_local][e], 24 KB

    int tid = threadIdx.x;
    int blk = blockIdx.x;           // b*64 + h*8 + s7
    int b   = blk >> 6;
    int h   = (blk >> 3) & 7;
    int s7  = blk & 7;
    int v   = 2 * s7 + h;                       // base0 = (32v + 256) mod 512
    int base0 = ((v << 5) + 256) & 511;

    int warp = tid >> 5, lane = tid & 31;
    int sub  = lane >> 4;           // which row of the pair
    int l    = lane & 15;           // e-slot: e = 4l..4l+3

    // ---- Prefetch V for this block's rows (pure input, overlaps everything) ----
    float4 vv[2];
    int    rowg[2];
    #pragma unroll
    for (int it = 0; it < 2; it++) {
        int s_hi = warp * 4 + it * 2 + sub;                 // 0..31
        int s    = s_hi * 8 + s7;
        rowg[it] = ((b * 8 + h) << 8) + s;                  // global row
        vv[it]   = reinterpret_cast<const float4*>(V)[rowg[it] * 16 + l];
    }

    // ---- Block u-range [uLo, uLo+len] (len < 0 -> all rows empty) ----
    int uLo = 0, len = -1;
    if (base0 <= 224)      { uLo = base0; len = min(base0 + 94, 255) - base0; }
    else if (base0 >= 448) { uLo = 0;     len = base0 - 418; }   // rows wrap to [0, base_row-449]

    if (len >= 0) {
        // ---- W compute: thread (us, e4); u_local = us + 16*iter ----
        int us = tid >> 4;
        int e4 = tid & 15;
        const float4* Q4 = reinterpret_cast<const float4*>(Q) + b * (PER_B / 4);
        const float4* V4 = reinterpret_cast<const float4*>(V) + b * (PER_B / 4);

        #pragma unroll
        for (int iter = 0; iter < 6; iter++) {
            int ul = us + (iter << 4);
            if (ul <= len) {
                // float4 index of (u*512 + r*64 + e4*4)
                int base4 = (uLo + ul) * 128 + e4;
                float4 acc = make_float4(0.f, 0.f, 0.f, 0.f);
                #pragma unroll
                for (int r = 0; r < 8; r++) {
                    float4 q = Q4[base4 + r * 16];
                    float4 w = V4[base4 + r * 16];
                    acc.x = fmaf(q.x, w.x, acc.x);
                    acc.y = fmaf(q.y, w.y, acc.y);
                    acc.z = fmaf(q.z, w.z, acc.z);
                    acc.w = fmaf(q.w, w.w, acc.w);
                }
                *reinterpret_cast<float4*>(&Wsm[ul][e4 * 4]) = acc;
            }
        }
        __syncthreads();

        // ---- In-place inclusive prefix along u (thread = e column) ----
        if (tid < 64) {
            float run = 0.f;
            #pragma unroll 4
            for (int i = 0; i <= len; i++) {
                run += Wsm[i][tid];
                Wsm[i][tid] = run;
            }
        }
        __syncthreads();
    }

    // ---- Rows: scores from smem prefix, softmax, outputs ----
    #pragma unroll
    for (int it = 0; it < 2; it++) {
        int s_hi     = warp * 4 + it * 2 + sub;
        int base_row = base0 + s_hi;                        // <= 511, no extra mod

        float4 sc = make_float4(0.f, 0.f, 0.f, 0.f);
        if (base_row < 256) {
            int lo = base_row;
            int hi = min(base_row + 63, 255);
            float4 hiV = *reinterpret_cast<const float4*>(&Wsm[hi - uLo][l * 4]);
            float4 loV = make_float4(0.f, 0.f, 0.f, 0.f);
            if (lo > uLo)
                loV = *reinterpret_cast<const float4*>(&Wsm[lo - uLo - 1][l * 4]);
            sc.x = hiV.x - loV.x;
            sc.y = hiV.y - loV.y;
            sc.z = hiV.z - loV.z;
            sc.w = hiV.w - loV.w;
        } else if (base_row > 448) {
            // wrap: window [0, base_row-449]; uLo == 0 so no low subtraction
            sc = *reinterpret_cast<const float4*>(&Wsm[base_row - 449][l * 4]);
        }
        // else: empty window -> sc = 0 -> uniform softmax

        // softmax over 64 e's: 4 per lane, reduce across the 16-lane half-warp.
        float m = fmaxf(fmaxf(sc.x, sc.y), fmaxf(sc.z, sc.w));
        #pragma unroll
        for (int d_ = 8; d_ > 0; d_ >>= 1)
            m = fmaxf(m, __shfl_xor_sync(0xffffffffu, m, d_));

        float e0 = __expf(sc.x - m);
        float e1 = __expf(sc.y - m);
        float e2 = __expf(sc.z - m);
        float e3 = __expf(sc.w - m);
        float ssum = (e0 + e1) + (e2 + e3);
        #pragma unroll
        for (int d_ = 8; d_ > 0; d_ >>= 1)
            ssum += __shfl_xor_sync(0xffffffffu, ssum, d_);
        float inv = __frcp_rn(ssum);

        float4 a = make_float4(e0 * inv, e1 * inv, e2 * inv, e3 * inv);
        float4 vvv = vv[it];

        int off4 = rowg[it] * 16 + l;
        reinterpret_cast<float4*>(out)[(OUT_HALF / 4) + off4] = a;          // attn
        reinterpret_cast<float4*>(out)[off4] =
            make_float4(a.x * vvv.x, a.y * vvv.y, a.z * vvv.z, a.w * vvv.w); // context
    }
}

extern "C" void kernel_launch(void* const* d_in, const int* in_sizes, int n_in,
                              void* d_out, int out_size) {
    const float* Q = (const float*)d_in[0];
    // d_in[1] (K) is genuinely unused by the reference computation.
    const float* V = (const float*)d_in[2];
    float* out = (float*)d_out;

    k_onepass<<<128, 256>>>(Q, V, out);
}

// round 8
// speedup vs baseline: 1.2204x; 1.2204x over previous
#include <cuda_runtime.h>

// Fixed shapes: B=2, H=8, S=256, d=64
#define PER_B 131072          // H*S*d floats per batch in Q/V
#define OUT_HALF 262144       // attn offset in out (context first, attn second)

// base_row(s) = (32*(2*s7+h) + 256 + s_hi) mod 512, window = [base_row, base_row+63] mod 512
// intersected with [0,256). v = 2*s7+h in {6..15} -> non-empty (4 (h,s7) combos each);
// all other v -> empty window -> uniform softmax.
__constant__ unsigned char c_light[24][2] = {  // {h, s7} pairs with v<=5 or v>=16
    {0,0},{1,0},{2,0},{0,1},{3,0},{1,1},{4,0},{2,1},{0,2},{5,0},{3,1},{1,2},
    {2,7},{4,6},{6,5},{3,7},{5,6},{7,5},{4,7},{6,6},{5,7},{7,6},{6,7},{7,7}
};

// Grid 48 x 1024. Blocks 0..39: heavy (b, v, s_hi-half). Blocks 40..47: light rows.
__global__ void __launch_bounds__(1024) k_onepass(const float* __restrict__ Q,
                                                  const float* __restrict__ V,
                                                  float* __restrict__ out) {
    int tid = threadIdx.x;
    int blk = blockIdx.x;
    const float4* V4g  = reinterpret_cast<const float4*>(V);
    float4*       out4 = reinterpret_cast<float4*>(out);

    if (blk >= 40) {
        // ---------------- Light: 1536 uniform rows (empty windows) ----------------
        const float inv = 1.0f / 64.0f;
        int k0 = (blk - 40) * 1024 + tid;
        #pragma unroll
        for (int it = 0; it < 3; it++) {
            int k = k0 + it * 8192;            // 24576 units total = 1536 rows * 16
            int r = k >> 4, l = k & 15;
            int b  = r / 768;
            int rr = r - b * 768;
            int pi = rr >> 5, s_hi = rr & 31;
            int h  = c_light[pi][0], s7 = c_light[pi][1];
            int grow = ((b * 8 + h) << 8) + s_hi * 8 + s7;
            float4 vv = V4g[grow * 16 + l];
            out4[(OUT_HALF / 4) + grow * 16 + l] = make_float4(inv, inv, inv, inv);
            out4[grow * 16 + l] =
                make_float4(vv.x * inv, vv.y * inv, vv.z * inv, vv.w * inv);
        }
        return;
    }

    // ---------------- Heavy: (b, v, sh) -> 64 rows, self-sufficient ----------------
    __shared__ float Wsm[80][64];   // [u_local][e], 20 KB

    int b   = (blk >= 20);
    int rem = blk - b * 20;
    int v   = 6 + (rem >> 1);
    int sh  = rem & 1;
    int base0 = ((v << 5) + 256) & 511;

    // Row mapping: one row per half-warp (64 half-warps = 64 rows).
    int hw = tid >> 4;              // 0..63
    int l  = tid & 15;              // e-slot: e = 4l..4l+3
    int combo = hw >> 4;            // 0..3
    int idx   = hw & 15;            // 0..15
    int s7min = max(0, (v - 6) >> 1);
    int s7 = s7min + combo;
    int h  = v - 2 * s7;
    int s_hi = sh * 16 + idx;
    int grow = ((b * 8 + h) << 8) + s_hi * 8 + s7;
    int base_row = base0 + s_hi;

    // Early V load for this row (overlaps the W compute below).
    float4 vv = V4g[grow * 16 + l];

    // Block u-window
    int uLo, uHi;
    bool wrap;
    if (base0 <= 224) { uLo = base0 + sh * 16; uHi = min(uLo + 78, 255); wrap = false; }
    else              { uLo = 0; uHi = base0 + sh * 16 + 15 - 449; wrap = true; }
    int len = uHi - uLo;            // <= 78

    // ---- W[u][e] = sum_r Q*V over the window (thread = (u_local, e4)) ----
    {
        int us = tid >> 4;          // 0..63
        int e4 = tid & 15;
        const float4* Q4 = reinterpret_cast<const float4*>(Q) + b * (PER_B / 4);
        const float4* W4 = reinterpret_cast<const float4*>(V) + b * (PER_B / 4);
        #pragma unroll
        for (int pass = 0; pass < 2; pass++) {
            int ul = us + pass * 64;
            if (ul <= len) {
                int base4 = (uLo + ul) * 128 + e4;   // float4 idx of (u*512 + e4*4)
                float4 acc = make_float4(0.f, 0.f, 0.f, 0.f);
                #pragma unroll
                for (int r = 0; r < 8; r++) {
                    float4 q = Q4[base4 + r * 16];
                    float4 w = W4[base4 + r * 16];
                    acc.x = fmaf(q.x, w.x, acc.x);
                    acc.y = fmaf(q.y, w.y, acc.y);
                    acc.z = fmaf(q.z, w.z, acc.z);
                    acc.w = fmaf(q.w, w.w, acc.w);
                }
                *reinterpret_cast<float4*>(&Wsm[ul][e4 * 4]) = acc;
            }
        }
    }
    __syncthreads();

    // ---- In-place inclusive prefix along u (thread = e column) ----
    if (tid < 64) {
        float run = 0.f;
        #pragma unroll 4
        for (int i = 0; i <= len; i++) {
            run += Wsm[i][tid];
            Wsm[i][tid] = run;
        }
    }
    __syncthreads();

    // ---- Score from prefix, softmax, outputs (1 row per half-warp) ----
    float4 sc = make_float4(0.f, 0.f, 0.f, 0.f);
    if (!wrap) {
        int hi = min(base_row + 63, 255);
        float4 hiV = *reinterpret_cast<const float4*>(&Wsm[hi - uLo][l * 4]);
        if (base_row > uLo) {
            float4 loV = *reinterpret_cast<const float4*>(&Wsm[base_row - 1 - uLo][l * 4]);
            sc = make_float4(hiV.x - loV.x, hiV.y - loV.y, hiV.z - loV.z, hiV.w - loV.w);
        } else {
            sc = hiV;
        }
    } else if (base_row > 448) {
        sc = *reinterpret_cast<const float4*>(&Wsm[base_row - 449][l * 4]);
    }
    // else: empty row inside heavy block -> sc = 0 -> uniform softmax

    float m = fmaxf(fmaxf(sc.x, sc.y), fmaxf(sc.z, sc.w));
    #pragma unroll
    for (int d_ = 8; d_ > 0; d_ >>= 1)
        m = fmaxf(m, __shfl_xor_sync(0xffffffffu, m, d_));

    float e0 = __expf(sc.x - m);
    float e1 = __expf(sc.y - m);
    float e2 = __expf(sc.z - m);
    float e3 = __expf(sc.w - m);
    float ssum = (e0 + e1) + (e2 + e3);
    #pragma unroll
    for (int d_ = 8; d_ > 0; d_ >>= 1)
        ssum += __shfl_xor_sync(0xffffffffu, ssum, d_);
    float inv = __frcp_rn(ssum);

    float4 a = make_float4(e0 * inv, e1 * inv, e2 * inv, e3 * inv);

    int off4 = grow * 16 + l;
    out4[(OUT_HALF / 4) + off4] = a;                                       // attn
    out4[off4] = make_float4(a.x * vv.x, a.y * vv.y, a.z * vv.z, a.w * vv.w); // context
}

extern "C" void kernel_launch(void* const* d_in, const int* in_sizes, int n_in,
                              void* d_out, int out_size) {
    const float* Q = (const float*)d_in[0];
    // d_in[1] (K) is genuinely unused by the reference computation.
    const float* V = (const float*)d_in[2];
    float* out = (float*)d_out;

    k_onepass<<<48, 1024>>>(Q, V, out);
}

// round 9
// speedup vs baseline: 1.3498x; 1.1060x over previous
#include <cuda_runtime.h>

// Fixed shapes: B=2, H=8, S=256, d=64
#define NB 2
#define NH 8
#define NS 256
#define ND 64
#define PER_B (NH*NS*ND)      // 131072 floats per batch in Q/V
#define OUT_HALF (NB*PER_B)   // 262144 floats: attn offset (context first, attn second)

// W[b][u][e] = sum_{r=0..7} Q[b*131072 + u*512 + r*64 + e] * V[same], u in [0,256)
// g_CP[b][c][i][e] = inclusive prefix of W over i within chunk c (u = c*64+i).
// Chunk total == g_CP[b][c][63][e].
__device__ float g_CP[NB][4][64][64];

// 64 blocks: blk = b*32 + c*8 + eq8 (eq8 = 8-wide e slice). 256 threads:
// tid = ul*4 + col*2 + rh  (ul: u_local 0..63, col: float4 within slice, rh: r half)
__global__ void __launch_bounds__(256) k_chunk_prefix(const float* __restrict__ Q,
                                                      const float* __restrict__ V) {
    int blk = blockIdx.x;
    int b   = blk >> 5;
    int c   = (blk >> 3) & 3;
    int eq8 = blk & 7;

    __shared__ float Wsm[64][8];

    int tid = threadIdx.x;
    int ul  = tid >> 2;
    int col = (tid >> 1) & 1;
    int rh  = tid & 1;

    const float4* Q4 = reinterpret_cast<const float4*>(Q) + b * (PER_B / 4);
    const float4* V4 = reinterpret_cast<const float4*>(V) + b * (PER_B / 4);

    // float4 index of (u*512 + r*64 + eq8*8 + col*4)
    int base4 = (c * 64 + ul) * 128 + eq8 * 2 + col + rh * 64;

    float4 acc = make_float4(0.f, 0.f, 0.f, 0.f);
    #pragma unroll
    for (int r = 0; r < 4; r++) {
        float4 q = Q4[base4 + r * 16];
        float4 v = V4[base4 + r * 16];
        acc.x = fmaf(q.x, v.x, acc.x);
        acc.y = fmaf(q.y, v.y, acc.y);
        acc.z = fmaf(q.z, v.z, acc.z);
        acc.w = fmaf(q.w, v.w, acc.w);
    }
    // combine the two r-halves (partner differs only in bit 0 of lane)
    acc.x += __shfl_xor_sync(0xffffffffu, acc.x, 1);
    acc.y += __shfl_xor_sync(0xffffffffu, acc.y, 1);
    acc.z += __shfl_xor_sync(0xffffffffu, acc.z, 1);
    acc.w += __shfl_xor_sync(0xffffffffu, acc.w, 1);
    if (rh == 0)
        *reinterpret_cast<float4*>(&Wsm[ul][col * 4]) = acc;
    __syncthreads();

    // Serial inclusive prefix along u for the 8 e-columns of this slice.
    if (tid < 8) {
        float a = 0.f;
        #pragma unroll
        for (int i = 0; i < 64; i++) {
            a += Wsm[i][tid];
            g_CP[b][c][i][eq8 * 8 + tid] = a;
        }
    }
}

// Grid 64 blocks x 512 threads (16 warps). Each warp handles 4 rows:
// row = blk*64 + warp*4 + it*2 + sub, it in {0,1}, sub = half-warp.
// Each lane covers 4 consecutive e's via float4. All CP loads for both
// iterations are issued before any consumption (MLP), then softmax + stores.
__global__ void __launch_bounds__(512) k_attn(const float* __restrict__ V,
                                              float* __restrict__ out) {
    int warp = threadIdx.x >> 5;
    int lane = threadIdx.x & 31;
    int sub  = lane >> 4;
    int l    = lane & 15;       // e-slot: covers e = 4l .. 4l+3

    const float4* CP4 = reinterpret_cast<const float4*>(g_CP);
    int row0 = blockIdx.x * 64 + warp * 4 + sub;

    float4 vv[2], hiV[2], loV[2], TT[2];
    int    cse[2];              // 0 empty, 1 single-chunk, 2 cross-chunk
    int    rows[2];

    #pragma unroll
    for (int it = 0; it < 2; it++) {
        int row = row0 + it * 2;            // ((b*8+h)*256+s)
        rows[it] = row;
        int b = row >> 11;
        int h = (row >> 8) & 7;
        int s = row & 255;

        // V load (pure input) issued early.
        vv[it] = reinterpret_cast<const float4*>(V)[row * 16 + l];

        // Circular window [base, base+63] mod 512 intersected with [0,256).
        int base = (((s & 7) << 6) + (h << 5) + (s >> 3) + 256) & 511;

        cse[it] = 0;
        hiV[it] = loV[it] = TT[it] = make_float4(0.f, 0.f, 0.f, 0.f);
        if (base < 256 || base > 448) {
            int lo, hi;
            if (base < 256) { lo = base; hi = min(base + 63, 255); }
            else            { lo = 0;    hi = base - 449; }          // wrap
            int c0 = lo >> 6, c1 = hi >> 6;   // c1 == c0 or c0+1
            int i0 = lo & 63, i1 = hi & 63;

            // float4 index of g_CP[b][c][i][4l] = ((b*4+c)*64 + i)*16 + l
            hiV[it] = CP4[((b * 4 + c1) * 64 + i1) * 16 + l];
            if (i0 > 0) loV[it] = CP4[((b * 4 + c0) * 64 + (i0 - 1)) * 16 + l];
            if (c0 == c1) {
                cse[it] = 1;
            } else {
                cse[it] = 2;
                TT[it] = CP4[((b * 4 + c0) * 64 + 63) * 16 + l];     // chunk total
            }
        }
    }

    #pragma unroll
    for (int it = 0; it < 2; it++) {
        float4 sc = make_float4(0.f, 0.f, 0.f, 0.f);
        if (cse[it] == 1) {
            sc.x = hiV[it].x - loV[it].x;
            sc.y = hiV[it].y - loV[it].y;
            sc.z = hiV[it].z - loV[it].z;
            sc.w = hiV[it].w - loV[it].w;
        } else if (cse[it] == 2) {
            sc.x = (TT[it].x - loV[it].x) + hiV[it].x;
            sc.y = (TT[it].y - loV[it].y) + hiV[it].y;
            sc.z = (TT[it].z - loV[it].z) + hiV[it].z;
            sc.w = (TT[it].w - loV[it].w) + hiV[it].w;
        }

        // softmax over 64 e's: 4 per lane, reduce across the 16-lane half-warp.
        float m = fmaxf(fmaxf(sc.x, sc.y), fmaxf(sc.z, sc.w));
        #pragma unroll
        for (int d_ = 8; d_ > 0; d_ >>= 1)
            m = fmaxf(m, __shfl_xor_sync(0xffffffffu, m, d_));

        float e0 = __expf(sc.x - m);
        float e1 = __expf(sc.y - m);
        float e2 = __expf(sc.z - m);
        float e3 = __expf(sc.w - m);
        float ssum = (e0 + e1) + (e2 + e3);
        #pragma unroll
        for (int d_ = 8; d_ > 0; d_ >>= 1)
            ssum += __shfl_xor_sync(0xffffffffu, ssum, d_);
        float inv = __frcp_rn(ssum);

        float4 a = make_float4(e0 * inv, e1 * inv, e2 * inv, e3 * inv);
        float4 v = vv[it];

        int off4 = rows[it] * 16 + l;
        reinterpret_cast<float4*>(out)[(OUT_HALF / 4) + off4] = a;        // attn
        reinterpret_cast<float4*>(out)[off4] =
            make_float4(a.x * v.x, a.y * v.y, a.z * v.z, a.w * v.w);      // context
    }
}

extern "C" void kernel_launch(void* const* d_in, const int* in_sizes, int n_in,
                              void* d_out, int out_size) {
    const float* Q = (const float*)d_in[0];
    // d_in[1] (K) is genuinely unused by the reference computation.
    const float* V = (const float*)d_in[2];
    float* out = (float*)d_out;

    k_chunk_prefix<<<64, 256>>>(Q, V);
    k_attn<<<64, 512>>>(V, out);
}